// round 1
// baseline (speedup 1.0000x reference)
#include <cuda_runtime.h>
#include <cstdint>

typedef unsigned long long ULL;

// ---------- packed f32x2 helpers (sm_100+ FFMA2 path) ----------
__device__ __forceinline__ ULL pack2(float lo, float hi) {
    ULL r; asm("mov.b64 %0, {%1, %2};" : "=l"(r) : "f"(lo), "f"(hi)); return r;
}
__device__ __forceinline__ void unpack2(ULL v, float& lo, float& hi) {
    asm("mov.b64 {%0, %1}, %2;" : "=f"(lo), "=f"(hi) : "l"(v));
}
__device__ __forceinline__ ULL ffma2(ULL a, ULL b, ULL c) {
    asm("fma.rn.f32x2 %0, %1, %2, %3;" : "=l"(c) : "l"(a), "l"(b), "l"(c)); return c;
}
__device__ __forceinline__ ULL fmul2(ULL a, ULL b) {
    ULL d; asm("mul.rn.f32x2 %0, %1, %2;" : "=l"(d) : "l"(a), "l"(b)); return d;
}

// ---------- problem constants ----------
#define BATCH 2
#define SEQ   2048
#define HID   1024
#define NH    16
#define HD    64
#define MTOT  (BATCH * SEQ)      // 4096 rows

// ---------- scratch (allocation-free rule: __device__ globals) ----------
__device__ float g_q[MTOT * HID];        // 16 MB
__device__ float g_kv[MTOT * 2 * HID];   // 32 MB
__device__ float g_y[MTOT * HID];        // 16 MB

// ============================================================================
// Generic SGEMM: C[M,N] = A[M,K] @ B[K,N], all row-major.
// 128x128 tile, BK=8, 256 threads, 8x8 microtile, f32x2 packed accumulators.
// Requires M%128==0, N%128==0, K%8==0 (true for all three uses).
// ============================================================================
__global__ __launch_bounds__(256) void gemm128(
    const float* __restrict__ A, const float* __restrict__ B,
    float* __restrict__ C, int M, int N, int K)
{
    __shared__ float As[8][128];   // As[k][m] (transposed on store)
    __shared__ float Bs[8][128];   // Bs[k][n]

    const int tid = threadIdx.x;
    const int tx = tid & 15, ty = tid >> 4;
    const int m0 = blockIdx.y * 128, n0 = blockIdx.x * 128;

    const int arow = tid >> 1, acol = (tid & 1) * 4;   // A tile: 128 rows x 8 cols
    const int brow = tid >> 5, bcol = (tid & 31) * 4;  // B tile: 8 rows x 128 cols

    const float* Aptr = A + (size_t)(m0 + arow) * K + acol;
    const float* Bptr = B + (size_t)brow * N + n0 + bcol;

    float4 av = *(const float4*)Aptr;
    float4 bv = *(const float4*)Bptr;

    ULL acc[8][4];
#pragma unroll
    for (int i = 0; i < 8; i++)
#pragma unroll
        for (int j = 0; j < 4; j++) acc[i][j] = 0ull;

    for (int k0 = 0; k0 < K; k0 += 8) {
        As[acol + 0][arow] = av.x;
        As[acol + 1][arow] = av.y;
        As[acol + 2][arow] = av.z;
        As[acol + 3][arow] = av.w;
        *(float4*)&Bs[brow][bcol] = bv;
        __syncthreads();

        if (k0 + 8 < K) {                       // prefetch next tile
            av = *(const float4*)(Aptr + k0 + 8);
            bv = *(const float4*)(Bptr + (size_t)(k0 + 8) * N);
        }

#pragma unroll
        for (int k = 0; k < 8; k++) {
            float4 a0 = *(const float4*)&As[k][ty * 8];
            float4 a1 = *(const float4*)&As[k][ty * 8 + 4];
            ULL b0 = *(const ULL*)&Bs[k][tx * 8];
            ULL b1 = *(const ULL*)&Bs[k][tx * 8 + 2];
            ULL b2 = *(const ULL*)&Bs[k][tx * 8 + 4];
            ULL b3 = *(const ULL*)&Bs[k][tx * 8 + 6];
            float a[8] = {a0.x, a0.y, a0.z, a0.w, a1.x, a1.y, a1.z, a1.w};
#pragma unroll
            for (int i = 0; i < 8; i++) {
                ULL ai = pack2(a[i], a[i]);
                acc[i][0] = ffma2(ai, b0, acc[i][0]);
                acc[i][1] = ffma2(ai, b1, acc[i][1]);
                acc[i][2] = ffma2(ai, b2, acc[i][2]);
                acc[i][3] = ffma2(ai, b3, acc[i][3]);
            }
        }
        __syncthreads();
    }

#pragma unroll
    for (int i = 0; i < 8; i++) {
        float f[8];
        unpack2(acc[i][0], f[0], f[1]);
        unpack2(acc[i][1], f[2], f[3]);
        unpack2(acc[i][2], f[4], f[5]);
        unpack2(acc[i][3], f[6], f[7]);
        float* Cp = C + (size_t)(m0 + ty * 8 + i) * N + n0 + tx * 8;
        *(float4*)Cp       = make_float4(f[0], f[1], f[2], f[3]);
        *(float4*)(Cp + 4) = make_float4(f[4], f[5], f[6], f[7]);
    }
}

// ============================================================================
// Fused flash attention, fp32, hd=64.
// Grid: (S/64, B*NH). CTA: 256 threads handles 64 q-rows of one (b,h).
// T processed in 64-row chunks; online softmax; P round-trips via smem
// (overlaying the K buffer). Dynamic smem: Qs[64][66]+Ks[64][66]+Vs[64][64].
// ============================================================================
#define ATTN_SMEM_FLOATS (2 * 64 * 66 + 64 * 64)
#define ATTN_SMEM_BYTES  (ATTN_SMEM_FLOATS * 4)

__global__ __launch_bounds__(256) void attn64(
    const float* __restrict__ Q, const float* __restrict__ KV,
    float* __restrict__ Y)
{
    extern __shared__ float sm[];
    float* Qs = sm;                 // [64][66] d-major, scaled q
    float* Ks = sm + 64 * 66;       // [64][66] d-major; reused as Ps[64][64]
    float* Vs = sm + 2 * 64 * 66;   // [64][64] t-major

    const int tid = threadIdx.x;
    const int tx = tid & 15, ty = tid >> 4;
    const int s0 = blockIdx.x * 64;
    const int bh = blockIdx.y;
    const int b = bh >> 4, h = bh & 15;

    const int lrow = tid >> 4;          // 0..15
    const int lcol = (tid & 15) * 4;    // 0..60

    // ---- load Q tile (pre-scaled by 1/sqrt(64)=0.125), transposed to [d][s]
    {
        const float* qbase = Q + ((size_t)b * SEQ + s0) * HID + h * HD;
#pragma unroll
        for (int l = 0; l < 4; l++) {
            int r = l * 16 + lrow;
            float4 v = *(const float4*)(qbase + (size_t)r * HID + lcol);
            Qs[(lcol + 0) * 66 + r] = v.x * 0.125f;
            Qs[(lcol + 1) * 66 + r] = v.y * 0.125f;
            Qs[(lcol + 2) * 66 + r] = v.z * 0.125f;
            Qs[(lcol + 3) * 66 + r] = v.w * 0.125f;
        }
    }

    float run_m[4], run_l[4];
    ULL o2[4][2];
#pragma unroll
    for (int i = 0; i < 4; i++) {
        run_m[i] = -1e30f; run_l[i] = 0.f;
        o2[i][0] = 0ull; o2[i][1] = 0ull;
    }

    const float* kbase = KV + (size_t)b * SEQ * (2 * HID) + h * HD;
    const float* vbase = kbase + HID;

    for (int t0 = 0; t0 < SEQ; t0 += 64) {
        __syncthreads();   // prev PV done reading Ps/Vs; also covers Q store on iter 0

        // ---- load K chunk transposed [d][t], V chunk [t][d]
#pragma unroll
        for (int l = 0; l < 4; l++) {
            int r = l * 16 + lrow;
            float4 kvv = *(const float4*)(kbase + (size_t)(t0 + r) * (2 * HID) + lcol);
            Ks[(lcol + 0) * 66 + r] = kvv.x;
            Ks[(lcol + 1) * 66 + r] = kvv.y;
            Ks[(lcol + 2) * 66 + r] = kvv.z;
            Ks[(lcol + 3) * 66 + r] = kvv.w;
            float4 vv = *(const float4*)(vbase + (size_t)(t0 + r) * (2 * HID) + lcol);
            *(float4*)&Vs[r * 64 + lcol] = vv;
        }
        __syncthreads();

        // ---- scores: s[4 rows][4 cols] per thread, rows ty*4+i, cols tx*4+j
        ULL s2[4][2];
#pragma unroll
        for (int i = 0; i < 4; i++) { s2[i][0] = 0ull; s2[i][1] = 0ull; }

#pragma unroll 4
        for (int d = 0; d < 64; d++) {
            ULL kb0 = *(const ULL*)&Ks[d * 66 + tx * 4];
            ULL kb1 = *(const ULL*)&Ks[d * 66 + tx * 4 + 2];
            float2 qa0 = *(const float2*)&Qs[d * 66 + ty * 4];
            float2 qa1 = *(const float2*)&Qs[d * 66 + ty * 4 + 2];
            float a[4] = {qa0.x, qa0.y, qa1.x, qa1.y};
#pragma unroll
            for (int i = 0; i < 4; i++) {
                ULL ai = pack2(a[i], a[i]);
                s2[i][0] = ffma2(ai, kb0, s2[i][0]);
                s2[i][1] = ffma2(ai, kb1, s2[i][1]);
            }
        }

        // ---- online softmax (row reductions across the 16-lane tx group)
        float p[4][4];
#pragma unroll
        for (int i = 0; i < 4; i++) {
            float s[4];
            unpack2(s2[i][0], s[0], s[1]);
            unpack2(s2[i][1], s[2], s[3]);
            float cm = fmaxf(fmaxf(s[0], s[1]), fmaxf(s[2], s[3]));
#pragma unroll
            for (int msk = 8; msk; msk >>= 1)
                cm = fmaxf(cm, __shfl_xor_sync(0xffffffffu, cm, msk, 16));
            float nm = fmaxf(run_m[i], cm);
            float alpha = __expf(run_m[i] - nm);
            run_m[i] = nm;
            float rs = 0.f;
#pragma unroll
            for (int j = 0; j < 4; j++) { p[i][j] = __expf(s[j] - nm); rs += p[i][j]; }
#pragma unroll
            for (int msk = 8; msk; msk >>= 1)
                rs += __shfl_xor_sync(0xffffffffu, rs, msk, 16);
            run_l[i] = run_l[i] * alpha + rs;
            ULL al2 = pack2(alpha, alpha);
            o2[i][0] = fmul2(o2[i][0], al2);
            o2[i][1] = fmul2(o2[i][1], al2);
        }
        __syncthreads();   // everyone done reading Ks before overlaying with P

        // ---- write P into Ks region (stride 64, row-major [s][t])
#pragma unroll
        for (int i = 0; i < 4; i++)
#pragma unroll
            for (int j = 0; j < 4; j++)
                Ks[(ty * 4 + i) * 64 + tx * 4 + j] = p[i][j];
        __syncthreads();

        // ---- O += P @ V
#pragma unroll 4
        for (int t = 0; t < 64; t++) {
            ULL vb0 = *(const ULL*)&Vs[t * 64 + tx * 4];
            ULL vb1 = *(const ULL*)&Vs[t * 64 + tx * 4 + 2];
#pragma unroll
            for (int i = 0; i < 4; i++) {
                float pv = Ks[(ty * 4 + i) * 64 + t];
                ULL ai = pack2(pv, pv);
                o2[i][0] = ffma2(ai, vb0, o2[i][0]);
                o2[i][1] = ffma2(ai, vb1, o2[i][1]);
            }
        }
    }

    // ---- epilogue: normalize and write y[b][s][h*64+d]
#pragma unroll
    for (int i = 0; i < 4; i++) {
        float f0, f1, f2, f3;
        unpack2(o2[i][0], f0, f1);
        unpack2(o2[i][1], f2, f3);
        float inv = 1.f / run_l[i];
        float* yp = Y + ((size_t)b * SEQ + s0 + ty * 4 + i) * HID + h * HD + tx * 4;
        *(float4*)yp = make_float4(f0 * inv, f1 * inv, f2 * inv, f3 * inv);
    }
}

// ============================================================================
// launch
// ============================================================================
extern "C" void kernel_launch(void* const* d_in, const int* in_sizes, int n_in,
                              void* d_out, int out_size)
{
    const float* query     = (const float*)d_in[0];  // [2,2048,1024]
    const float* key_value = (const float*)d_in[1];  // [2,2048,1024]
    const float* Wq        = (const float*)d_in[2];  // [1024,1024]
    const float* Wkv       = (const float*)d_in[3];  // [1024,2048]
    const float* Wc        = (const float*)d_in[4];  // [1024,1024]
    float* out = (float*)d_out;                      // [2,2048,1024]

    float *qs, *kvs, *ys;
    cudaGetSymbolAddress((void**)&qs, g_q);
    cudaGetSymbolAddress((void**)&kvs, g_kv);
    cudaGetSymbolAddress((void**)&ys, g_y);

    cudaFuncSetAttribute(attn64, cudaFuncAttributeMaxDynamicSharedMemorySize,
                         ATTN_SMEM_BYTES);

    // q = query @ Wq          : [4096,1024] x [1024,1024]
    gemm128<<<dim3(HID / 128, MTOT / 128), 256>>>(query, Wq, qs, MTOT, HID, HID);
    // kv = key_value @ Wkv    : [4096,1024] x [1024,2048]
    gemm128<<<dim3(2 * HID / 128, MTOT / 128), 256>>>(key_value, Wkv, kvs, MTOT, 2 * HID, HID);
    // attention               : 32 s-tiles x 32 (b,h)
    attn64<<<dim3(SEQ / 64, BATCH * NH), 256, ATTN_SMEM_BYTES>>>(qs, kvs, ys);
    // out = y @ Wc            : [4096,1024] x [1024,1024]
    gemm128<<<dim3(HID / 128, MTOT / 128), 256>>>(ys, Wc, out, MTOT, HID, HID);
}